// round 3
// baseline (speedup 1.0000x reference)
#include <cuda_runtime.h>
#include <stdint.h>

#define N_ATOMS 1024
#define NFEAT   80
#define NIRR    48
#define K3      1270
#define K2      24
#define K1      3
#define M3      (NIRR*NIRR*NIRR)   // 110592
#define PQ      (NIRR*NIRR)        // 2304
#define PSPLIT  4
#define PRNG    (NIRR/PSPLIT)      // 12
#define OUTSZ   (N_ATOMS*NFEAT)    // 81920

typedef unsigned long long ull;

// ---- device scratch (no allocation allowed) ----
__device__ float2 g_UW3[(size_t)NFEAT * M3];   // dup-packed {v,v}: 70.8 MB
__device__ float  g_C2W[NFEAT * PQ];
__device__ float  g_C1W[NFEAT * NIRR];
__device__ float  g_part[PSPLIT * OUTSZ];

// ---- packed f32x2 + async-copy helpers (sm_103a) ----
__device__ __forceinline__ ull pack2(float x, float y){ull r;asm("mov.b64 %0,{%1,%2};":"=l"(r):"f"(x),"f"(y));return r;}
__device__ __forceinline__ void unpack2(ull v,float&x,float&y){asm("mov.b64 {%0,%1},%2;":"=f"(x),"=f"(y):"l"(v));}
__device__ __forceinline__ ull fma2(ull a,ull b,ull c){ull d;asm("fma.rn.f32x2 %0,%1,%2,%3;":"=l"(d):"l"(a),"l"(b),"l"(c));return d;}
__device__ __forceinline__ ull add2(ull a,ull b){ull d;asm("add.rn.f32x2 %0,%1,%2;":"=l"(d):"l"(a),"l"(b));return d;}
__device__ __forceinline__ uint32_t s2u(const void* p){uint32_t a;asm("{.reg .u64 t;cvta.to.shared.u64 t,%1;cvt.u32.u64 %0,t;}":"=r"(a):"l"(p));return a;}
// 8-byte cp.async: U3 rows are only 8B-aligned (K3*4 = 5080 ≡ 8 mod 16)
__device__ __forceinline__ void cpa8(uint32_t d,const void* s,int bytes){asm volatile("cp.async.ca.shared.global [%0],[%1],8,%2;"::"r"(d),"l"(s),"r"(bytes));}
__device__ __forceinline__ void cpa16(uint32_t d,const void* s,int bytes){asm volatile("cp.async.ca.shared.global [%0],[%1],16,%2;"::"r"(d),"l"(s),"r"(bytes));}
__device__ __forceinline__ void cpa16f(uint32_t d,const void* s){asm volatile("cp.async.ca.shared.global [%0],[%1],16;"::"r"(d),"l"(s));}
__device__ __forceinline__ void cp_commit(){asm volatile("cp.async.commit_group;");}
__device__ __forceinline__ void cp_wait1(){asm volatile("cp.async.wait_group 1;"::: "memory");}
__device__ __forceinline__ void cp_wait0(){asm volatile("cp.async.wait_group 0;"::: "memory");}

// ============================================================
// k_small: C2W[c,pq] = sum_k U2[pq,k] W2[k,c];  C1W[c,p] = sum_k U1[p,k] W1[k,c]
// grid 9 x 256: one thread per pq, U2 read once.
// ============================================================
__global__ __launch_bounds__(256) void k_small(
    const float* __restrict__ U2, const float* __restrict__ W2,
    const float* __restrict__ U1, const float* __restrict__ W1)
{
    __shared__ float w2s[K2 * NFEAT];
    int t = threadIdx.x;
    for (int i = t; i < K2 * NFEAT; i += 256) w2s[i] = W2[i];
    __syncthreads();

    int pq = blockIdx.x * 256 + t;
    float u[K2];
    #pragma unroll
    for (int k = 0; k < K2; k++) u[k] = U2[(size_t)pq * K2 + k];
    for (int cc = 0; cc < NFEAT; cc++) {
        float s = 0.f;
        #pragma unroll
        for (int k = 0; k < K2; k++) s += u[k] * w2s[k * NFEAT + cc];
        g_C2W[cc * PQ + pq] = s;
    }
    if (blockIdx.x == 0 && t < NIRR) {
        float a0 = U1[t*3], a1 = U1[t*3+1], a2v = U1[t*3+2];
        for (int cc = 0; cc < NFEAT; cc++)
            g_C1W[cc * NIRR + t] = a0*W1[cc] + a1*W1[NFEAT+cc] + a2v*W1[2*NFEAT+cc];
    }
}

// ============================================================
// k_gemm1: UW3[c,m] = sum_k U3[m,k] W3[k,c]  (stored dup {v,v})
// cp.async double-buffered. 256 thr = 32(m-lane) x 8(c-group).
// ============================================================
#define BK 32
#define NT ((K3 + BK - 1) / BK)     // 40
#define AS_STRIDE 36                // padded floats per A row
#define AS_BYTES (128 * AS_STRIDE * 4)   // 18432
#define BS_BYTES (BK * 40 * 8)           // 10240
#define G1_SMEM (2*AS_BYTES + 2*BS_BYTES) // 57344

__global__ __launch_bounds__(256) void k_gemm1(
    const float* __restrict__ U3, const float* __restrict__ W3)
{
    extern __shared__ char smc[];
    float* As = (float*)smc;                  // [2][128][36]
    ull*   Bs = (ull*)(smc + 2*AS_BYTES);     // [2][32][40] float2 pairs
    uint32_t As_u = s2u(As), Bs_u = s2u(Bs);

    int t  = threadIdx.x;
    int ty = t & 31, tx = t >> 5;
    int m0 = blockIdx.x * 128;

    int lr = t & 127;            // A-load row
    int lh = (t >> 7) * 16;      // A-load k offset (floats)

    ull acc[4][5];
    #pragma unroll
    for (int j = 0; j < 4; j++)
        #pragma unroll
        for (int u = 0; u < 5; u++) acc[j][u] = 0ull;

    auto loadTile = [&](int tile, int buf) {
        int kc = tile * BK;
        const float* srcA = U3 + (size_t)(m0 + lr) * K3;
        uint32_t dA = As_u + buf * AS_BYTES + (lr * AS_STRIDE + lh) * 4;
        // A: 8-byte cp.async pairs (row base only 8B-aligned)
        #pragma unroll
        for (int ci = 0; ci < 4; ci++) {
            int kg = kc + lh + 4 * ci;
            int b0 = (K3 - kg) * 4;       b0 = b0 < 0 ? 0 : (b0 > 8 ? 8 : b0);
            int b1 = (K3 - kg - 2) * 4;   b1 = b1 < 0 ? 0 : (b1 > 8 ? 8 : b1);
            cpa8(dA + 16 * ci,     srcA + (b0 > 0 ? kg     : 0), b0);
            cpa8(dA + 16 * ci + 8, srcA + (b1 > 0 ? kg + 2 : 0), b1);
        }
        // B: 16B cp.async (W3 rows are 320B-strided, 16B-aligned)
        #pragma unroll
        for (int j = 0; j < 3; j++) {
            int idx = t + 256 * j;
            if (idx < 640) {
                int row = idx / 20, c16 = idx % 20;
                int kg = kc + row;
                int bytes = (kg < K3) ? 16 : 0;
                const float* srcB = W3 + (size_t)(bytes > 0 ? kg : 0) * NFEAT + c16 * 4;
                cpa16(Bs_u + buf * BS_BYTES + row * 320 + c16 * 16, srcB, bytes);
            }
        }
        cp_commit();
    };

    loadTile(0, 0);
    for (int tile = 0; tile < NT; tile++) {
        int buf = tile & 1;
        __syncthreads();                       // prev compute done before overwriting buf^1
        if (tile + 1 < NT) { loadTile(tile + 1, buf ^ 1); cp_wait1(); }
        else               { cp_wait0(); }
        __syncthreads();                       // all threads' copies of buf visible

        const float* Ab = As + buf * 128 * AS_STRIDE;
        const ull*   Bb = Bs + buf * BK * 40;
        #pragma unroll 8
        for (int kk = 0; kk < BK; kk++) {
            ull b2[5];
            #pragma unroll
            for (int u = 0; u < 5; u++) b2[u] = Bb[kk * 40 + tx + 8 * u];  // LDS.64 -> pair
            #pragma unroll
            for (int j = 0; j < 4; j++) {
                float a = Ab[(ty + 32 * j) * AS_STRIDE + kk];
                ull a2 = pack2(a, a);
                #pragma unroll
                for (int u = 0; u < 5; u++) acc[j][u] = fma2(a2, b2[u], acc[j][u]);
            }
        }
    }

    #pragma unroll
    for (int j = 0; j < 4; j++) {
        int m = m0 + ty + 32 * j;
        #pragma unroll
        for (int u = 0; u < 5; u++) {
            int c0 = 2 * (tx + 8 * u);
            float lo, hi; unpack2(acc[j][u], lo, hi);
            g_UW3[(size_t)c0 * M3 + m]       = make_float2(lo, lo);
            g_UW3[(size_t)(c0 + 1) * M3 + m] = make_float2(hi, hi);
        }
    }
}

// ============================================================
// k_zero: zeroes g_part (also keeps k_main at profile launch slot)
// ============================================================
__global__ void k_zero() {
    int i = blockIdx.x * 256 + threadIdx.x;
    if (i < PSPLIT * OUTSZ) g_part[i] = 0.f;
}

// ============================================================
// k_main: partial over p-range of 12.
// grid (4 n-chunks, 80 c, 4 p-splits) = 1280 blocks, 128 thr, 2 atoms/thread.
// cp.async double-buffered uw staging.
// ============================================================
#define TPB 128
#define UW_BYTES (PQ * 8)                                     // 18432
#define MAIN_SMEM (2*UW_BYTES + TPB*49*8 + PRNG*NIRR*8 + 64)  // 91712

__global__ __launch_bounds__(TPB) void k_main(const float* __restrict__ nf)
{
    extern __shared__ char smc[];
    float2* uw   = (float2*)smc;                                  // [2][2304] dup
    ull*    nfsm = (ull*)(smc + 2*UW_BYTES);                      // [128][49]
    ull*    c2u  = (ull*)(smc + 2*UW_BYTES + TPB*49*8);           // [12][48] dup
    float*  c1s  = (float*)(smc + 2*UW_BYTES + TPB*49*8 + PRNG*NIRR*8);
    uint32_t uw_u = s2u(uw);

    int t  = threadIdx.x;
    int c  = blockIdx.y;
    int P0 = blockIdx.z * PRNG;
    int nA = (blockIdx.x * TPB + t) * 2;

    const float* fa = nf + (size_t)nA * (NFEAT * NIRR) + c * NIRR;
    const float* fb = fa + NFEAT * NIRR;

    ull nf2[NIRR];
    ull* myrow = nfsm + t * 49;
    #pragma unroll
    for (int i4 = 0; i4 < 12; i4++) {
        float4 a = *(const float4*)(fa + 4 * i4);
        float4 b = *(const float4*)(fb + 4 * i4);
        nf2[4*i4+0] = pack2(a.x, b.x);  myrow[4*i4+0] = nf2[4*i4+0];
        nf2[4*i4+1] = pack2(a.y, b.y);  myrow[4*i4+1] = nf2[4*i4+1];
        nf2[4*i4+2] = pack2(a.z, b.z);  myrow[4*i4+2] = nf2[4*i4+2];
        nf2[4*i4+3] = pack2(a.w, b.w);  myrow[4*i4+3] = nf2[4*i4+3];
    }
    for (int idx = t; idx < PRNG * NIRR; idx += TPB) {
        float v = g_C2W[c * PQ + (P0 + idx / NIRR) * NIRR + (idx % NIRR)];
        c2u[idx] = pack2(v, v);
    }
    if (t < PRNG) c1s[t] = g_C1W[c * NIRR + P0 + t];

    const char* uwg = (const char*)(g_UW3 + (size_t)c * M3 + (size_t)P0 * PQ);

    auto stage = [&](int pp, int buf) {
        const char* src = uwg + (size_t)pp * UW_BYTES;
        uint32_t dst = uw_u + buf * UW_BYTES;
        #pragma unroll
        for (int j = 0; j < 9; j++) cpa16f(dst + (t + TPB * j) * 16, src + (t + TPB * j) * 16);
        cp_commit();
    };

    ull acc = 0ull;
    stage(0, 0);
    for (int pp = 0; pp < PRNG; pp++) {
        int buf = pp & 1;
        __syncthreads();                         // prev compute done; also covers c2u/c1s init
        if (pp + 1 < PRNG) { stage(pp + 1, buf ^ 1); cp_wait1(); }
        else               { cp_wait0(); }
        __syncthreads();

        float c1 = c1s[pp];
        ull tp = pack2(c1, c1);
        const float2* uwb = uw + buf * PQ;
        #pragma unroll 4
        for (int q = 0; q < NIRR; q++) {
            ull s0 = c2u[pp * NIRR + q], s1 = 0ull, s2 = 0ull, s3 = 0ull;
            const ulonglong2* uq = (const ulonglong2*)(uwb + q * NIRR);
            #pragma unroll
            for (int ii = 0; ii < 12; ii++) {
                ulonglong2 u0 = uq[2 * ii];
                ulonglong2 u1 = uq[2 * ii + 1];
                s0 = fma2(nf2[4*ii+0], u0.x, s0);
                s1 = fma2(nf2[4*ii+1], u0.y, s1);
                s2 = fma2(nf2[4*ii+2], u1.x, s2);
                s3 = fma2(nf2[4*ii+3], u1.y, s3);
            }
            tp = fma2(myrow[q], add2(add2(s0, s1), add2(s2, s3)), tp);
        }
        acc = fma2(myrow[P0 + pp], tp, acc);
    }

    float oa, ob; unpack2(acc, oa, ob);
    g_part[blockIdx.z * OUTSZ + nA * NFEAT + c]       = oa;
    g_part[blockIdx.z * OUTSZ + (nA + 1) * NFEAT + c] = ob;
}

// ============================================================
__global__ void k_reduce(float* __restrict__ out) {
    int i = blockIdx.x * 256 + threadIdx.x;
    if (i < OUTSZ)
        out[i] = (g_part[i] + g_part[OUTSZ + i]) + (g_part[2*OUTSZ + i] + g_part[3*OUTSZ + i]);
}

// ============================================================
extern "C" void kernel_launch(void* const* d_in, const int* in_sizes, int n_in,
                              void* d_out, int out_size)
{
    const float* nf = (const float*)d_in[0];
    const float* U3 = (const float*)d_in[1];
    const float* U2 = (const float*)d_in[2];
    const float* U1 = (const float*)d_in[3];
    const float* W3 = (const float*)d_in[4];
    const float* W2 = (const float*)d_in[5];
    const float* W1 = (const float*)d_in[6];
    float* out = (float*)d_out;

    cudaFuncSetAttribute(k_gemm1, cudaFuncAttributeMaxDynamicSharedMemorySize, G1_SMEM);
    cudaFuncSetAttribute(k_main,  cudaFuncAttributeMaxDynamicSharedMemorySize, MAIN_SMEM);

    k_small<<<PQ / 256, 256>>>(U2, W2, U1, W1);
    k_gemm1<<<M3 / 128, 256, G1_SMEM>>>(U3, W3);
    k_zero<<<(PSPLIT * OUTSZ + 255) / 256, 256>>>();
    k_main<<<dim3(N_ATOMS / (2 * TPB), NFEAT, PSPLIT), TPB, MAIN_SMEM>>>(nf);
    k_reduce<<<(OUTSZ + 255) / 256, 256>>>(out);
}

// round 4
// speedup vs baseline: 1.3187x; 1.3187x over previous
#include <cuda_runtime.h>
#include <stdint.h>

#define N_ATOMS 1024
#define NFEAT   80
#define NIRR    48
#define K3      1270
#define K2      24
#define K1      3
#define M3      (NIRR*NIRR*NIRR)   // 110592
#define PQ      (NIRR*NIRR)        // 2304
#define PSPLIT  8
#define PRNG    (NIRR/PSPLIT)      // 6
#define OUTSZ   (N_ATOMS*NFEAT)    // 81920

typedef unsigned long long ull;

// ---- device scratch ----
__device__ float2 g_UW3[(size_t)NFEAT * M3];   // dup-packed {v,v}: 70.8 MB
__device__ float  g_C2W[NFEAT * PQ];
__device__ float  g_C1W[NFEAT * NIRR];
__device__ float  g_part[PSPLIT * OUTSZ];

// ---- packed f32x2 + async-copy helpers (sm_103a) ----
__device__ __forceinline__ ull pack2(float x, float y){ull r;asm("mov.b64 %0,{%1,%2};":"=l"(r):"f"(x),"f"(y));return r;}
__device__ __forceinline__ void unpack2(ull v,float&x,float&y){asm("mov.b64 {%0,%1},%2;":"=f"(x),"=f"(y):"l"(v));}
__device__ __forceinline__ ull fma2(ull a,ull b,ull c){ull d;asm("fma.rn.f32x2 %0,%1,%2,%3;":"=l"(d):"l"(a),"l"(b),"l"(c));return d;}
__device__ __forceinline__ ull add2(ull a,ull b){ull d;asm("add.rn.f32x2 %0,%1,%2;":"=l"(d):"l"(a),"l"(b));return d;}
__device__ __forceinline__ uint32_t s2u(const void* p){uint32_t a;asm("{.reg .u64 t;cvta.to.shared.u64 t,%1;cvt.u32.u64 %0,t;}":"=r"(a):"l"(p));return a;}
__device__ __forceinline__ void cpa8(uint32_t d,const void* s,int bytes){asm volatile("cp.async.ca.shared.global [%0],[%1],8,%2;"::"r"(d),"l"(s),"r"(bytes));}
__device__ __forceinline__ void cpa16(uint32_t d,const void* s,int bytes){asm volatile("cp.async.ca.shared.global [%0],[%1],16,%2;"::"r"(d),"l"(s),"r"(bytes));}
__device__ __forceinline__ void cpa16f(uint32_t d,const void* s){asm volatile("cp.async.ca.shared.global [%0],[%1],16;"::"r"(d),"l"(s));}
__device__ __forceinline__ void cp_commit(){asm volatile("cp.async.commit_group;");}
__device__ __forceinline__ void cp_wait1(){asm volatile("cp.async.wait_group 1;"::: "memory");}
__device__ __forceinline__ void cp_wait0(){asm volatile("cp.async.wait_group 0;"::: "memory");}

// ============================================================
// k_small: C2W + C1W precompute (one U2 read)
// ============================================================
__global__ __launch_bounds__(256) void k_small(
    const float* __restrict__ U2, const float* __restrict__ W2,
    const float* __restrict__ U1, const float* __restrict__ W1)
{
    __shared__ float w2s[K2 * NFEAT];
    int t = threadIdx.x;
    for (int i = t; i < K2 * NFEAT; i += 256) w2s[i] = W2[i];
    __syncthreads();

    int pq = blockIdx.x * 256 + t;
    float u[K2];
    #pragma unroll
    for (int k = 0; k < K2; k++) u[k] = U2[(size_t)pq * K2 + k];
    for (int cc = 0; cc < NFEAT; cc++) {
        float s = 0.f;
        #pragma unroll
        for (int k = 0; k < K2; k++) s += u[k] * w2s[k * NFEAT + cc];
        g_C2W[cc * PQ + pq] = s;
    }
    if (blockIdx.x == 0 && t < NIRR) {
        float a0 = U1[t*3], a1 = U1[t*3+1], a2v = U1[t*3+2];
        for (int cc = 0; cc < NFEAT; cc++)
            g_C1W[cc * NIRR + t] = a0*W1[cc] + a1*W1[NFEAT+cc] + a2v*W1[2*NFEAT+cc];
    }
}

// ============================================================
// k_gemm1: UW3[c,m] = sum_k U3[m,k] W3[k,c]  (stored dup {v,v})
// A consumed via conflict-free LDS.128 (stride 36, 4 consecutive k).
// ============================================================
#define BK 32
#define NT ((K3 + BK - 1) / BK)     // 40
#define AS_STRIDE 36
#define AS_BYTES (128 * AS_STRIDE * 4)   // 18432
#define BS_BYTES (BK * 40 * 8)           // 10240
#define G1_SMEM (2*AS_BYTES + 2*BS_BYTES) // 57344

__global__ __launch_bounds__(256) void k_gemm1(
    const float* __restrict__ U3, const float* __restrict__ W3)
{
    extern __shared__ char smc[];
    float* As = (float*)smc;                  // [2][128][36]
    ull*   Bs = (ull*)(smc + 2*AS_BYTES);     // [2][32][40]
    uint32_t As_u = s2u(As), Bs_u = s2u(Bs);

    int t  = threadIdx.x;
    int ty = t & 31, tx = t >> 5;
    int m0 = blockIdx.x * 128;

    int lr = t & 127;            // A-load row
    int lh = (t >> 7) * 16;      // A-load k offset (floats)

    ull acc[4][5];
    #pragma unroll
    for (int j = 0; j < 4; j++)
        #pragma unroll
        for (int u = 0; u < 5; u++) acc[j][u] = 0ull;

    auto loadTile = [&](int tile, int buf) {
        int kc = tile * BK;
        const float* srcA = U3 + (size_t)(m0 + lr) * K3;
        uint32_t dA = As_u + buf * AS_BYTES + (lr * AS_STRIDE + lh) * 4;
        #pragma unroll
        for (int ci = 0; ci < 4; ci++) {
            int kg = kc + lh + 4 * ci;
            int b0 = (K3 - kg) * 4;       b0 = b0 < 0 ? 0 : (b0 > 8 ? 8 : b0);
            int b1 = (K3 - kg - 2) * 4;   b1 = b1 < 0 ? 0 : (b1 > 8 ? 8 : b1);
            cpa8(dA + 16 * ci,     srcA + (b0 > 0 ? kg     : 0), b0);
            cpa8(dA + 16 * ci + 8, srcA + (b1 > 0 ? kg + 2 : 0), b1);
        }
        #pragma unroll
        for (int j = 0; j < 3; j++) {
            int idx = t + 256 * j;
            if (idx < 640) {
                int row = idx / 20, c16 = idx % 20;
                int kg = kc + row;
                int bytes = (kg < K3) ? 16 : 0;
                const float* srcB = W3 + (size_t)(bytes > 0 ? kg : 0) * NFEAT + c16 * 4;
                cpa16(Bs_u + buf * BS_BYTES + row * 320 + c16 * 16, srcB, bytes);
            }
        }
        cp_commit();
    };

    loadTile(0, 0);
    for (int tile = 0; tile < NT; tile++) {
        int buf = tile & 1;
        __syncthreads();
        if (tile + 1 < NT) { loadTile(tile + 1, buf ^ 1); cp_wait1(); }
        else               { cp_wait0(); }
        __syncthreads();

        const float* Ab = As + buf * 128 * AS_STRIDE;
        const ull*   Bb = Bs + buf * BK * 40;
        #pragma unroll
        for (int kkb = 0; kkb < BK / 4; kkb++) {
            ull b2[4][5];
            #pragma unroll
            for (int e = 0; e < 4; e++)
                #pragma unroll
                for (int u = 0; u < 5; u++)
                    b2[e][u] = Bb[(kkb * 4 + e) * 40 + tx + 8 * u];   // broadcast LDS.64
            #pragma unroll
            for (int j = 0; j < 4; j++) {
                float4 av = *(const float4*)(Ab + (ty + 32 * j) * AS_STRIDE + kkb * 4); // conflict-free LDS.128
                ull a0 = pack2(av.x, av.x), a1 = pack2(av.y, av.y);
                ull a2 = pack2(av.z, av.z), a3 = pack2(av.w, av.w);
                #pragma unroll
                for (int u = 0; u < 5; u++) {
                    acc[j][u] = fma2(a0, b2[0][u], acc[j][u]);
                    acc[j][u] = fma2(a1, b2[1][u], acc[j][u]);
                    acc[j][u] = fma2(a2, b2[2][u], acc[j][u]);
                    acc[j][u] = fma2(a3, b2[3][u], acc[j][u]);
                }
            }
        }
    }

    #pragma unroll
    for (int j = 0; j < 4; j++) {
        int m = m0 + ty + 32 * j;
        #pragma unroll
        for (int u = 0; u < 5; u++) {
            int c0 = 2 * (tx + 8 * u);
            float lo, hi; unpack2(acc[j][u], lo, hi);
            g_UW3[(size_t)c0 * M3 + m]       = make_float2(lo, lo);
            g_UW3[(size_t)(c0 + 1) * M3 + m] = make_float2(hi, hi);
        }
    }
}

// ============================================================
__global__ void k_zero() {
    int i = blockIdx.x * 256 + threadIdx.x;
    if (i < PSPLIT * OUTSZ) g_part[i] = 0.f;
}

// ============================================================
// k_main: partial over p-range of PRNG=6. nf kept entirely in registers;
// q-loop fully unrolled so nf2[q] is compile-time indexed.
// grid (4 n-chunks, 80 c, 8 p-splits) = 2560 blocks, 128 thr, 2 atoms/thread.
// ============================================================
#define TPB 128
#define UW_BYTES (PQ * 8)                                 // 18432
#define MAIN_SMEM (2*UW_BYTES + PRNG*NIRR*8 + PRNG*4 + 32) // ~39224

__global__ __launch_bounds__(TPB, 3) void k_main(const float* __restrict__ nf)
{
    extern __shared__ char smc[];
    float2* uw  = (float2*)smc;                           // [2][2304] dup
    ull*    c2u = (ull*)(smc + 2*UW_BYTES);               // [6][48] dup
    float*  c1s = (float*)(smc + 2*UW_BYTES + PRNG*NIRR*8);
    uint32_t uw_u = s2u(uw);

    int t  = threadIdx.x;
    int c  = blockIdx.y;
    int P0 = blockIdx.z * PRNG;
    int nA = (blockIdx.x * TPB + t) * 2;

    const float* fa = nf + (size_t)nA * (NFEAT * NIRR) + c * NIRR;
    const float* fb = fa + NFEAT * NIRR;

    ull nf2[NIRR];
    #pragma unroll
    for (int i4 = 0; i4 < 12; i4++) {
        float4 a = *(const float4*)(fa + 4 * i4);
        float4 b = *(const float4*)(fb + 4 * i4);
        nf2[4*i4+0] = pack2(a.x, b.x);
        nf2[4*i4+1] = pack2(a.y, b.y);
        nf2[4*i4+2] = pack2(a.z, b.z);
        nf2[4*i4+3] = pack2(a.w, b.w);
    }
    for (int idx = t; idx < PRNG * NIRR; idx += TPB) {
        float v = g_C2W[c * PQ + (P0 + idx / NIRR) * NIRR + (idx % NIRR)];
        c2u[idx] = pack2(v, v);
    }
    if (t < PRNG) c1s[t] = g_C1W[c * NIRR + P0 + t];

    const char* uwg = (const char*)(g_UW3 + (size_t)c * M3 + (size_t)P0 * PQ);

    auto stage = [&](int pp, int buf) {
        const char* src = uwg + (size_t)pp * UW_BYTES;
        uint32_t dst = uw_u + buf * UW_BYTES;
        #pragma unroll
        for (int j = 0; j < 9; j++) cpa16f(dst + (t + TPB * j) * 16, src + (t + TPB * j) * 16);
        cp_commit();
    };

    ull acc = 0ull;
    stage(0, 0);
    for (int pp = 0; pp < PRNG; pp++) {
        int buf = pp & 1;
        __syncthreads();                 // prev compute done; covers c2u/c1s init on pp=0
        if (pp + 1 < PRNG) { stage(pp + 1, buf ^ 1); cp_wait1(); }
        else               { cp_wait0(); }
        __syncthreads();

        float c1 = c1s[pp];
        ull tp = pack2(c1, c1);
        const float2* uwb = uw + buf * PQ;
        #pragma unroll
        for (int q = 0; q < NIRR; q++) {
            ull s0 = c2u[pp * NIRR + q], s1 = 0ull, s2 = 0ull, s3 = 0ull;  // broadcast
            const ulonglong2* uq = (const ulonglong2*)(uwb + q * NIRR);
            #pragma unroll
            for (int ii = 0; ii < 12; ii++) {
                ulonglong2 u0 = uq[2 * ii];       // broadcast LDS.128
                ulonglong2 u1 = uq[2 * ii + 1];
                s0 = fma2(nf2[4*ii+0], u0.x, s0);
                s1 = fma2(nf2[4*ii+1], u0.y, s1);
                s2 = fma2(nf2[4*ii+2], u1.x, s2);
                s3 = fma2(nf2[4*ii+3], u1.y, s3);
            }
            tp = fma2(nf2[q], add2(add2(s0, s1), add2(s2, s3)), tp);   // compile-time q
        }
        // p-multiplier via L1-hit LDG (avoids runtime-indexed register array)
        float pa = fa[P0 + pp], pb = fb[P0 + pp];
        acc = fma2(pack2(pa, pb), tp, acc);
    }

    float oa, ob; unpack2(acc, oa, ob);
    g_part[blockIdx.z * OUTSZ + nA * NFEAT + c]       = oa;
    g_part[blockIdx.z * OUTSZ + (nA + 1) * NFEAT + c] = ob;
}

// ============================================================
__global__ void k_reduce(float* __restrict__ out) {
    int i = blockIdx.x * 256 + threadIdx.x;
    if (i < OUTSZ) {
        float s = 0.f;
        #pragma unroll
        for (int z = 0; z < PSPLIT; z++) s += g_part[z * OUTSZ + i];
        out[i] = s;
    }
}

// ============================================================
extern "C" void kernel_launch(void* const* d_in, const int* in_sizes, int n_in,
                              void* d_out, int out_size)
{
    const float* nf = (const float*)d_in[0];
    const float* U3 = (const float*)d_in[1];
    const float* U2 = (const float*)d_in[2];
    const float* U1 = (const float*)d_in[3];
    const float* W3 = (const float*)d_in[4];
    const float* W2 = (const float*)d_in[5];
    const float* W1 = (const float*)d_in[6];
    float* out = (float*)d_out;

    cudaFuncSetAttribute(k_gemm1, cudaFuncAttributeMaxDynamicSharedMemorySize, G1_SMEM);
    cudaFuncSetAttribute(k_main,  cudaFuncAttributeMaxDynamicSharedMemorySize, MAIN_SMEM);

    k_small<<<PQ / 256, 256>>>(U2, W2, U1, W1);
    k_gemm1<<<M3 / 128, 256, G1_SMEM>>>(U3, W3);
    k_zero<<<(PSPLIT * OUTSZ + 255) / 256, 256>>>();
    k_main<<<dim3(N_ATOMS / (2 * TPB), NFEAT, PSPLIT), TPB, MAIN_SMEM>>>(nf);
    k_reduce<<<(OUTSZ + 255) / 256, 256>>>(out);
}

// round 5
// speedup vs baseline: 2.1845x; 1.6565x over previous
#include <cuda_runtime.h>
#include <stdint.h>

#define N_ATOMS 1024
#define NFEAT   80
#define NIRR    48
#define K3      1270
#define K2      24
#define NPAIR   1176     // #(p<=q)
#define NELEM   21424    // quad-padded canonical triple elements
#define STAGE   1248     // padded row-set size for p=0 (all q rows)
#define ZSPLIT  2
#define OUTSZ   (N_ATOMS*NFEAT)

typedef unsigned long long ull;

// ---- device scratch ----
__device__ __align__(16) float2 g_UW3[(size_t)NFEAT * NELEM + 4]; // dup {v,v}: 13.7MB
__device__ __align__(16) float2 g_S2W[NFEAT * NPAIR];             // dup symmetrized pair coefs
__device__ float  g_S1W[NFEAT * NIRR];
__device__ float  g_part[ZSPLIT * OUTSZ];

// ---- helpers ----
__device__ __forceinline__ ull pack2(float x, float y){ull r;asm("mov.b64 %0,{%1,%2};":"=l"(r):"f"(x),"f"(y));return r;}
__device__ __forceinline__ void unpack2(ull v,float&x,float&y){asm("mov.b64 {%0,%1},%2;":"=f"(x),"=f"(y):"l"(v));}
__device__ __forceinline__ ull fma2(ull a,ull b,ull c){ull d;asm("fma.rn.f32x2 %0,%1,%2,%3;":"=l"(d):"l"(a),"l"(b),"l"(c));return d;}
__device__ __forceinline__ ull add2(ull a,ull b){ull d;asm("add.rn.f32x2 %0,%1,%2;":"=l"(d):"l"(a),"l"(b));return d;}
__device__ __forceinline__ ull mul2(ull a,ull b){ull d;asm("mul.rn.f32x2 %0,%1,%2;":"=l"(d):"l"(a),"l"(b));return d;}
__device__ __forceinline__ uint32_t s2u(const void* p){uint32_t a;asm("{.reg .u64 t;cvta.to.shared.u64 t,%1;cvt.u32.u64 %0,t;}":"=r"(a):"l"(p));return a;}
__device__ __forceinline__ void cpa16(uint32_t d,const void* s,int bytes){asm volatile("cp.async.ca.shared.global [%0],[%1],16,%2;"::"r"(d),"l"(s),"r"(bytes));}
__device__ __forceinline__ void cpa16f(uint32_t d,const void* s){asm volatile("cp.async.ca.shared.global [%0],[%1],16;"::"r"(d),"l"(s));}
__device__ __forceinline__ void cp_commit(){asm volatile("cp.async.commit_group;");}
__device__ __forceinline__ void cp_wait1(){asm volatile("cp.async.wait_group 1;"::: "memory");}
__device__ __forceinline__ void cp_wait0(){asm volatile("cp.async.wait_group 0;"::: "memory");}

// padded-prefix: LOFF(p) = sum_{q<p} (48 - 4*(q/4))
__device__ __forceinline__ int loff_f(int p){ int a=p>>2, b=p&3; return 48*p - 8*a*(a-1) - 4*a*b; }
__device__ __forceinline__ int tpad_f(int p){ return STAGE - loff_f(p); }

// ============================================================
// k_small: symmetrized pair coefficients S2W + linear S1W
// thread = (p,q); active p<=q writes S2W[c, r(p,q)] = C2W[p,q]+C2W[q,p] (p<q) / C2W[p,p]
// ============================================================
__global__ __launch_bounds__(256) void k_small(
    const float* __restrict__ U2, const float* __restrict__ W2,
    const float* __restrict__ U1, const float* __restrict__ W1)
{
    __shared__ float w2s[K2 * NFEAT];
    int t = threadIdx.x;
    for (int i = t; i < K2 * NFEAT; i += 256) w2s[i] = W2[i];
    __syncthreads();

    int pq = blockIdx.x * 256 + t;
    int p = pq / NIRR, q = pq % NIRR;
    if (p <= q) {
        float u[K2], ut[K2];
        #pragma unroll
        for (int k = 0; k < K2; k++) u[k] = U2[(size_t)(p * NIRR + q) * K2 + k];
        #pragma unroll
        for (int k = 0; k < K2; k++) ut[k] = (p == q) ? 0.f : U2[(size_t)(q * NIRR + p) * K2 + k];
        int r = p * NIRR - p * (p - 1) / 2 + (q - p);
        for (int cc = 0; cc < NFEAT; cc++) {
            float s = 0.f;
            #pragma unroll
            for (int k = 0; k < K2; k++) s += (u[k] + ut[k]) * w2s[k * NFEAT + cc];
            g_S2W[cc * NPAIR + r] = make_float2(s, s);
        }
    }
    if (blockIdx.x == 0 && t < NIRR) {
        float a0 = U1[t*3], a1 = U1[t*3+1], a2v = U1[t*3+2];
        for (int cc = 0; cc < NFEAT; cc++)
            g_S1W[cc * NIRR + t] = a0*W1[cc] + a1*W1[NFEAT+cc] + a2v*W1[2*NFEAT+cc];
    }
}

// ============================================================
// k_gemm1: S3W[c,e] = sum_k S3U[e,k] W3[k,c], with S3U[e,k] gathered on the fly:
// element e -> canonical (p<=q<=i) (quad-padded); S3U = sum over <=6 distinct perms of U3.
// M=21424 (168 tiles of 128), K=1270, N=80. A via LDG-gather+STS, B via cp.async. Dup store.
// ============================================================
#define BK 32
#define NT ((K3 + BK - 1) / BK)          // 40
#define AS_STRIDE 36
#define AS_BYTES (128 * AS_STRIDE * 4)   // 18432
#define BS_BYTES (BK * 40 * 8)           // 10240
#define G1_SMEM (2*AS_BYTES + 2*BS_BYTES)

__global__ __launch_bounds__(256, 2) void k_gemm1(
    const float* __restrict__ U3, const float* __restrict__ W3)
{
    extern __shared__ char smc[];
    float* As = (float*)smc;
    ull*   Bs = (ull*)(smc + 2*AS_BYTES);
    uint32_t Bs_u = s2u(Bs);

    int t  = threadIdx.x;
    int ty = t & 31, tx = t >> 5;
    int m0 = blockIdx.x * 128;

    int lr = t & 127;            // element row within tile
    int lh = (t >> 7) * 16;      // k offset (16 floats per thread)

    // --- invert element -> (p,q,i); build distinct-perm base offsets
    long long base[6];
    int np = 0;
    {
        int e = m0 + lr;
        if (e < NELEM) {
            int rem = e, p = 0, q = 0;
            for (p = 0; p < NIRR; p++) { int Tp = tpad_f(p); if (rem < Tp) break; rem -= Tp; }
            for (q = p; q < NIRR; q++) { int L = NIRR - (q & ~3); if (rem < L) break; rem -= L; }
            int i = (q & ~3) + rem;
            if (i >= q) {   // not a pad slot
                auto addp = [&](int a, int b, int cc) {
                    base[np++] = (long long)((a * NIRR + b) * NIRR + cc) * K3;
                };
                addp(p, q, i);
                if (p == q && q == i) { /* 1 perm */ }
                else if (p == q) { addp(p, i, p); addp(i, p, p); }
                else if (q == i) { addp(q, p, q); addp(q, q, p); }
                else { addp(p, i, q); addp(q, p, i); addp(q, i, p); addp(i, p, q); addp(i, q, p); }
            }
        }
    }

    ull acc[4][5];
    #pragma unroll
    for (int j = 0; j < 4; j++)
        #pragma unroll
        for (int u = 0; u < 5; u++) acc[j][u] = 0ull;

    float vals[16];

    auto gatherA = [&](int tile) {
        int kg0 = tile * BK + lh;
        #pragma unroll
        for (int s = 0; s < 16; s++) vals[s] = 0.f;
        for (int j = 0; j < np; j++) {
            const float2* src = (const float2*)(U3 + base[j] + kg0);  // 8B aligned
            #pragma unroll
            for (int s = 0; s < 8; s++) {
                if (kg0 + 2*s < K3) {           // K3 even: pairwise guard exact
                    float2 x = src[s];
                    vals[2*s] += x.x; vals[2*s+1] += x.y;
                }
            }
        }
    };
    auto loadB = [&](int tile, int buf) {
        int kc = tile * BK;
        #pragma unroll
        for (int j = 0; j < 3; j++) {
            int idx = t + 256 * j;
            if (idx < 640) {
                int row = idx / 20, c16 = idx % 20;
                int kg = kc + row;
                int bytes = (kg < K3) ? 16 : 0;
                const float* srcB = W3 + (size_t)(bytes > 0 ? kg : 0) * NFEAT + c16 * 4;
                cpa16(Bs_u + buf * BS_BYTES + row * 320 + c16 * 16, srcB, bytes);
            }
        }
        cp_commit();
    };

    gatherA(0);
    loadB(0, 0);
    for (int tile = 0; tile < NT; tile++) {
        int buf = tile & 1;
        __syncthreads();                         // A[buf]/B[buf^1] free
        // STS gathered A into buffer
        float4* dst = (float4*)(As + buf * 128 * AS_STRIDE + lr * AS_STRIDE + lh);
        dst[0] = make_float4(vals[0], vals[1], vals[2],  vals[3]);
        dst[1] = make_float4(vals[4], vals[5], vals[6],  vals[7]);
        dst[2] = make_float4(vals[8], vals[9], vals[10], vals[11]);
        dst[3] = make_float4(vals[12],vals[13], vals[14], vals[15]);
        if (tile + 1 < NT) { gatherA(tile + 1); loadB(tile + 1, buf ^ 1); cp_wait1(); }
        else               { cp_wait0(); }
        __syncthreads();

        const float* Ab = As + buf * 128 * AS_STRIDE;
        const ull*   Bb = Bs + buf * BK * 40;
        #pragma unroll
        for (int kkb = 0; kkb < BK / 4; kkb++) {
            ull b2[4][5];
            #pragma unroll
            for (int e = 0; e < 4; e++)
                #pragma unroll
                for (int u = 0; u < 5; u++)
                    b2[e][u] = Bb[(kkb * 4 + e) * 40 + tx + 8 * u];
            #pragma unroll
            for (int j = 0; j < 4; j++) {
                float4 av = *(const float4*)(Ab + (ty + 32 * j) * AS_STRIDE + kkb * 4);
                ull a0 = pack2(av.x, av.x), a1 = pack2(av.y, av.y);
                ull a2 = pack2(av.z, av.z), a3 = pack2(av.w, av.w);
                #pragma unroll
                for (int u = 0; u < 5; u++) {
                    acc[j][u] = fma2(a0, b2[0][u], acc[j][u]);
                    acc[j][u] = fma2(a1, b2[1][u], acc[j][u]);
                    acc[j][u] = fma2(a2, b2[2][u], acc[j][u]);
                    acc[j][u] = fma2(a3, b2[3][u], acc[j][u]);
                }
            }
        }
    }

    #pragma unroll
    for (int j = 0; j < 4; j++) {
        int m = m0 + ty + 32 * j;
        if (m < NELEM) {
            #pragma unroll
            for (int u = 0; u < 5; u++) {
                int c0 = 2 * (tx + 8 * u);
                float lo, hi; unpack2(acc[j][u], lo, hi);
                g_UW3[(size_t)c0 * NELEM + m]       = make_float2(lo, lo);
                g_UW3[(size_t)(c0 + 1) * NELEM + m] = make_float2(hi, hi);
            }
        }
    }
}

// ============================================================
__global__ void k_zero() {
    int i = blockIdx.x * 256 + threadIdx.x;
    if (i < ZSPLIT * OUTSZ) g_part[i] = 0.f;
}

// ============================================================
// k_main: out_part[n,c] over owned p (p = z, z+2, ...):
//   acc += x_p * x_q * ( S2[r(p,q)] + sum_{i} S3row[p,q][i] * x_i ),  rows quad-padded
// z==0 also adds sum_p S1[p] x_p. grid (4, 80, 2), 128 thr, 2 atoms/thread (f32x2).
// ============================================================
#define TPB 128
#define MAIN_SMEM (2*STAGE*8 + NPAIR*8 + NIRR*8)   // 19968+9408+384 = 29760

__global__ __launch_bounds__(TPB, 3) void k_main(const float* __restrict__ nf)
{
    extern __shared__ char smc[];
    ull* stg   = (ull*)smc;                            // [2][1248] dup S3 rows for one p
    ull* s2dup = (ull*)(smc + 2*STAGE*8);              // [1176]
    ull* s1dup = (ull*)(smc + 2*STAGE*8 + NPAIR*8);    // [48]
    uint32_t stg_u = s2u(stg);
    uint32_t s2_u  = s2u(s2dup);

    int t  = threadIdx.x;
    int c  = blockIdx.y;
    int z  = blockIdx.z;
    int nA = (blockIdx.x * TPB + t) * 2;

    const float* fa = nf + (size_t)nA * (NFEAT * NIRR) + c * NIRR;
    const float* fb = fa + NFEAT * NIRR;

    ull nf2[NIRR];
    #pragma unroll
    for (int i4 = 0; i4 < 12; i4++) {
        float4 a = *(const float4*)(fa + 4 * i4);
        float4 b = *(const float4*)(fb + 4 * i4);
        nf2[4*i4+0] = pack2(a.x, b.x);
        nf2[4*i4+1] = pack2(a.y, b.y);
        nf2[4*i4+2] = pack2(a.z, b.z);
        nf2[4*i4+3] = pack2(a.w, b.w);
    }
    // stage S2 (group 0)
    for (int j = t; j < NPAIR / 2; j += TPB)
        cpa16f(s2_u + 16 * j, (const char*)(g_S2W + c * NPAIR) + 16 * j);
    cp_commit();
    // S1 dup via STS
    if (t < NIRR) { float v = g_S1W[c * NIRR + t]; s1dup[t] = pack2(v, v); }

    const float2* uwc = g_UW3 + (size_t)c * NELEM;

    auto stage = [&](int p, int buf, int off3) {
        int lo  = loff_f(p);
        int nch = (STAGE - lo) >> 1;                   // 16B chunks
        const char* src = (const char*)(uwc + off3);
        uint32_t dst = stg_u + (buf * STAGE + lo) * 8;
        for (int j = t; j < nch; j += TPB) cpa16f(dst + 16 * j, src + 16 * j);
        cp_commit();
    };

    ull acc = 0ull;
    int off_cur = (z == 0) ? 0 : STAGE;                // OFF3(0)=0, OFF3(1)=Tpad(0)=1248
    stage(z, 0, off_cur);                              // group 1

    for (int p = z; p < NIRR; p += 2) {
        int buf = ((p - z) >> 1) & 1;
        __syncthreads();                               // prev compute done
        int off_next = off_cur + tpad_f(p) + tpad_f(p + 1);
        if (p + 2 < NIRR) { stage(p + 2, buf ^ 1, off_next); cp_wait1(); }
        else              { cp_wait0(); }
        __syncthreads();

        ull x2p = pack2(fa[p], fb[p]);                 // L1-hit LDGs (runtime p)
        int rbase = p * NIRR - p * (p - 1) / 2 - p;    // r(p,q) = rbase + q
        const ull* sb = stg + buf * STAGE;

        int lofq = 0;
        #pragma unroll
        for (int q = 0; q < NIRR; q++) {
            const int q4 = q >> 2;
            if (q >= p) {
                ull t0 = s2dup[rbase + q], t1 = 0ull, t2 = 0ull, t3 = 0ull;
                const ulonglong2* row = (const ulonglong2*)(sb + lofq);
                #pragma unroll
                for (int i4 = q4; i4 < 12; i4++) {
                    ulonglong2 u0 = row[2 * (i4 - q4)];
                    ulonglong2 u1 = row[2 * (i4 - q4) + 1];
                    t0 = fma2(nf2[4*i4+0], u0.x, t0);
                    t1 = fma2(nf2[4*i4+1], u0.y, t1);
                    t2 = fma2(nf2[4*i4+2], u1.x, t2);
                    t3 = fma2(nf2[4*i4+3], u1.y, t3);
                }
                ull w = mul2(x2p, nf2[q]);
                acc = fma2(w, add2(add2(t0, t1), add2(t2, t3)), acc);
            }
            lofq += NIRR - 4 * q4;                     // compile-time running offset
        }
        off_cur = off_next;
    }

    if (z == 0) {                                      // linear term once
        #pragma unroll
        for (int q = 0; q < NIRR; q++) acc = fma2(nf2[q], s1dup[q], acc);
    }

    float oa, ob; unpack2(acc, oa, ob);
    g_part[z * OUTSZ + nA * NFEAT + c]       = oa;
    g_part[z * OUTSZ + (nA + 1) * NFEAT + c] = ob;
}

// ============================================================
__global__ void k_reduce(float* __restrict__ out) {
    int i = blockIdx.x * 256 + threadIdx.x;
    if (i < OUTSZ) out[i] = g_part[i] + g_part[OUTSZ + i];
}

// ============================================================
extern "C" void kernel_launch(void* const* d_in, const int* in_sizes, int n_in,
                              void* d_out, int out_size)
{
    const float* nf = (const float*)d_in[0];
    const float* U3 = (const float*)d_in[1];
    const float* U2 = (const float*)d_in[2];
    const float* U1 = (const float*)d_in[3];
    const float* W3 = (const float*)d_in[4];
    const float* W2 = (const float*)d_in[5];
    const float* W1 = (const float*)d_in[6];
    float* out = (float*)d_out;

    cudaFuncSetAttribute(k_gemm1, cudaFuncAttributeMaxDynamicSharedMemorySize, G1_SMEM);
    cudaFuncSetAttribute(k_main,  cudaFuncAttributeMaxDynamicSharedMemorySize, MAIN_SMEM);

    k_small<<<(NIRR*NIRR) / 256, 256>>>(U2, W2, U1, W1);
    k_gemm1<<<(NELEM + 127) / 128, 256, G1_SMEM>>>(U3, W3);
    k_zero<<<(ZSPLIT * OUTSZ + 255) / 256, 256>>>();
    k_main<<<dim3(N_ATOMS / (2 * TPB), NFEAT, ZSPLIT), TPB, MAIN_SMEM>>>(nf);
    k_reduce<<<(OUTSZ + 255) / 256, 256>>>(out);
}

// round 6
// speedup vs baseline: 3.0085x; 1.3772x over previous
#include <cuda_runtime.h>
#include <stdint.h>

#define N_ATOMS 1024
#define NFEAT   80
#define NIRR    48
#define K3      1270
#define K2      24
#define NPAIR   1176     // #(p<=q)
#define NELEM   21424    // quad-padded canonical triple elements
#define MPAD    21504    // 168*128 (GEMM row padding)
#define KPAD    1280     // S3U row stride (zeros past 1269)
#define STAGE   1248     // padded row-set size for p=0 (all q rows)
#define ZSPLIT  2
#define OUTSZ   (N_ATOMS*NFEAT)

typedef unsigned long long ull;

// ---- device scratch ----
__device__ __align__(16) float  g_S3U[(size_t)MPAD * KPAD];       // dense symmetrized: 110MB
__device__ __align__(16) float2 g_UW3[(size_t)NFEAT * NELEM + 4]; // dup {v,v}: 13.7MB
__device__ __align__(16) float2 g_S2W[NFEAT * NPAIR];
__device__ float  g_S1W[NFEAT * NIRR];
__device__ float  g_part[ZSPLIT * OUTSZ];

// ---- helpers ----
__device__ __forceinline__ ull pack2(float x, float y){ull r;asm("mov.b64 %0,{%1,%2};":"=l"(r):"f"(x),"f"(y));return r;}
__device__ __forceinline__ void unpack2(ull v,float&x,float&y){asm("mov.b64 {%0,%1},%2;":"=f"(x),"=f"(y):"l"(v));}
__device__ __forceinline__ ull fma2(ull a,ull b,ull c){ull d;asm("fma.rn.f32x2 %0,%1,%2,%3;":"=l"(d):"l"(a),"l"(b),"l"(c));return d;}
__device__ __forceinline__ ull add2(ull a,ull b){ull d;asm("add.rn.f32x2 %0,%1,%2;":"=l"(d):"l"(a),"l"(b));return d;}
__device__ __forceinline__ ull mul2(ull a,ull b){ull d;asm("mul.rn.f32x2 %0,%1,%2;":"=l"(d):"l"(a),"l"(b));return d;}
__device__ __forceinline__ uint32_t s2u(const void* p){uint32_t a;asm("{.reg .u64 t;cvta.to.shared.u64 t,%1;cvt.u32.u64 %0,t;}":"=r"(a):"l"(p));return a;}
__device__ __forceinline__ void cpa16(uint32_t d,const void* s,int bytes){asm volatile("cp.async.ca.shared.global [%0],[%1],16,%2;"::"r"(d),"l"(s),"r"(bytes));}
__device__ __forceinline__ void cpa16f(uint32_t d,const void* s){asm volatile("cp.async.ca.shared.global [%0],[%1],16;"::"r"(d),"l"(s));}
__device__ __forceinline__ void cp_commit(){asm volatile("cp.async.commit_group;");}
__device__ __forceinline__ void cp_wait1(){asm volatile("cp.async.wait_group 1;"::: "memory");}
__device__ __forceinline__ void cp_wait0(){asm volatile("cp.async.wait_group 0;"::: "memory");}

// padded-prefix: LOFF(p) = sum_{q<p} (48 - 4*(q/4))
__device__ __forceinline__ int loff_f(int p){ int a=p>>2, b=p&3; return 48*p - 8*a*(a-1) - 4*a*b; }
__device__ __forceinline__ int tpad_f(int p){ return STAGE - loff_f(p); }

// ============================================================
// k_small: symmetrized pair coefficients S2W + linear S1W
// ============================================================
__global__ __launch_bounds__(256) void k_small(
    const float* __restrict__ U2, const float* __restrict__ W2,
    const float* __restrict__ U1, const float* __restrict__ W1)
{
    __shared__ float w2s[K2 * NFEAT];
    int t = threadIdx.x;
    for (int i = t; i < K2 * NFEAT; i += 256) w2s[i] = W2[i];
    __syncthreads();

    int pq = blockIdx.x * 256 + t;
    int p = pq / NIRR, q = pq % NIRR;
    if (p <= q) {
        float u[K2], ut[K2];
        #pragma unroll
        for (int k = 0; k < K2; k++) u[k] = U2[(size_t)(p * NIRR + q) * K2 + k];
        #pragma unroll
        for (int k = 0; k < K2; k++) ut[k] = (p == q) ? 0.f : U2[(size_t)(q * NIRR + p) * K2 + k];
        int r = p * NIRR - p * (p - 1) / 2 + (q - p);
        for (int cc = 0; cc < NFEAT; cc++) {
            float s = 0.f;
            #pragma unroll
            for (int k = 0; k < K2; k++) s += (u[k] + ut[k]) * w2s[k * NFEAT + cc];
            g_S2W[cc * NPAIR + r] = make_float2(s, s);
        }
    }
    if (blockIdx.x == 0 && t < NIRR) {
        float a0 = U1[t*3], a1 = U1[t*3+1], a2v = U1[t*3+2];
        for (int cc = 0; cc < NFEAT; cc++)
            g_S1W[cc * NIRR + t] = a0*W1[cc] + a1*W1[NFEAT+cc] + a2v*W1[2*NFEAT+cc];
    }
}

// ============================================================
// k_symm: dense symmetrization. warp = one canonical element e -> (p<=q<=i);
// S3U[e][k] = sum over <=6 distinct index perms of U3[perm][k]. Coalesced.
// grid 2678 x 256 (8 warps = 8 elements/block).
// ============================================================
__global__ __launch_bounds__(256) void k_symm(const float* __restrict__ U3)
{
    int w = threadIdx.x >> 5, lane = threadIdx.x & 31;
    int el = blockIdx.x * 8 + w;

    int rem = el, p, q;
    for (p = 0; p < NIRR; p++) { int Tp = tpad_f(p); if (rem < Tp) break; rem -= Tp; }
    for (q = p; q < NIRR; q++) { int L = NIRR - (q & ~3); if (rem < L) break; rem -= L; }
    int i = (q & ~3) + rem;

    long long base[6]; int np = 0;
    if (i >= q) {
        auto addp = [&](int a, int b, int cc) {
            base[np++] = (long long)((a * NIRR + b) * NIRR + cc) * K3;
        };
        addp(p, q, i);
        if (p == q && q == i) { }
        else if (p == q) { addp(p, i, p); addp(i, p, p); }
        else if (q == i) { addp(q, p, q); addp(q, q, p); }
        else { addp(p, i, q); addp(q, p, i); addp(q, i, p); addp(i, p, q); addp(i, q, p); }
    }

    float acc[40];
    #pragma unroll
    for (int s = 0; s < 40; s++) acc[s] = 0.f;
    for (int j = 0; j < np; j++) {
        const float* r = U3 + base[j];
        #pragma unroll
        for (int s = 0; s < 40; s++) {
            int k = 32 * s + lane;
            if (k < K3) acc[s] += __ldg(r + k);     // coalesced 128B per load
        }
    }
    float* dst = g_S3U + (size_t)el * KPAD;
    #pragma unroll
    for (int s = 0; s < 40; s++) dst[32 * s + lane] = acc[s];   // zeros pad k>=1270
}

// ============================================================
// k_gemm1: UW3[c,e] = sum_k S3U[e,k] W3[k,c]  (stored dup {v,v})
// Dense cp.async double-buffered GEMM. M=21504(pad), K=1280(pad), N=80.
// grid (168, 2 c-halves), 128 thr = 32(m) x 4(c-group of 5 pairs). 4 CTAs/SM.
// ============================================================
#define BK 32
#define NT 40
#define AS_STRIDE 36
#define AS_BYTES (128 * AS_STRIDE * 4)   // 18432
#define BS_BYTES (BK * 20 * 8)           // 5120
#define G1_SMEM (2*AS_BYTES + 2*BS_BYTES) // 47104

__global__ __launch_bounds__(128, 4) void k_gemm1(const float* __restrict__ W3)
{
    extern __shared__ char smc[];
    float* As = (float*)smc;                  // [2][128][36]
    ull*   Bs = (ull*)(smc + 2*AS_BYTES);     // [2][32][20]
    uint32_t As_u = s2u(As), Bs_u = s2u(Bs);

    int t  = threadIdx.x;
    int ty = t & 31, tx = t >> 5;
    int m0 = blockIdx.x * 128;
    int cblk = blockIdx.y;

    ull acc[4][5];
    #pragma unroll
    for (int j = 0; j < 4; j++)
        #pragma unroll
        for (int u = 0; u < 5; u++) acc[j][u] = 0ull;

    auto loadTile = [&](int tile, int buf) {
        int kc = tile * BK;
        // A: thread t loads full 32-float k-chunk of row m0+t (8x cpa16, all aligned)
        const char* srcA = (const char*)(g_S3U + (size_t)(m0 + t) * KPAD + kc);
        uint32_t dA = As_u + buf * AS_BYTES + t * (AS_STRIDE * 4);
        #pragma unroll
        for (int i = 0; i < 8; i++) cpa16f(dA + 16 * i, srcA + 16 * i);
        // B: 32 rows x 20 c-pairs (guard k >= K3 -> zero-fill)
        #pragma unroll
        for (int j = 0; j < 3; j++) {
            int idx = t + 128 * j;
            if (idx < 320) {
                int row = idx / 10, c16 = idx % 10;
                int kg = kc + row;
                int bytes = (kg < K3) ? 16 : 0;
                const float* srcB = W3 + (size_t)(bytes > 0 ? kg : 0) * NFEAT + cblk * 40 + c16 * 4;
                cpa16(Bs_u + buf * BS_BYTES + row * 160 + c16 * 16, srcB, bytes);
            }
        }
        cp_commit();
    };

    loadTile(0, 0);
    for (int tile = 0; tile < NT; tile++) {
        int buf = tile & 1;
        __syncthreads();
        if (tile + 1 < NT) { loadTile(tile + 1, buf ^ 1); cp_wait1(); }
        else               { cp_wait0(); }
        __syncthreads();

        const float* Ab = As + buf * 128 * AS_STRIDE;
        const ull*   Bb = Bs + buf * BK * 20;
        #pragma unroll
        for (int kkb = 0; kkb < BK / 4; kkb++) {
            ull b2[4][5];
            #pragma unroll
            for (int e = 0; e < 4; e++)
                #pragma unroll
                for (int u = 0; u < 5; u++)
                    b2[e][u] = Bb[(kkb * 4 + e) * 20 + tx + 4 * u];   // warp-uniform broadcast
            #pragma unroll
            for (int j = 0; j < 4; j++) {
                float4 av = *(const float4*)(Ab + (ty + 32 * j) * AS_STRIDE + kkb * 4);
                ull a0 = pack2(av.x, av.x), a1 = pack2(av.y, av.y);
                ull a2 = pack2(av.z, av.z), a3 = pack2(av.w, av.w);
                #pragma unroll
                for (int u = 0; u < 5; u++) {
                    acc[j][u] = fma2(a0, b2[0][u], acc[j][u]);
                    acc[j][u] = fma2(a1, b2[1][u], acc[j][u]);
                    acc[j][u] = fma2(a2, b2[2][u], acc[j][u]);
                    acc[j][u] = fma2(a3, b2[3][u], acc[j][u]);
                }
            }
        }
    }

    #pragma unroll
    for (int j = 0; j < 4; j++) {
        int m = m0 + ty + 32 * j;
        if (m < NELEM) {
            #pragma unroll
            for (int u = 0; u < 5; u++) {
                int c0 = 2 * (cblk * 20 + tx + 4 * u);
                float lo, hi; unpack2(acc[j][u], lo, hi);
                g_UW3[(size_t)c0 * NELEM + m]       = make_float2(lo, lo);
                g_UW3[(size_t)(c0 + 1) * NELEM + m] = make_float2(hi, hi);
            }
        }
    }
}

// ============================================================
// k_main: out_part[n,c] over owned p (p = z, z+2, ...):
//   acc += x_p * x_q * ( S2[r(p,q)] + sum_i S3row[p,q][i] * x_i )
// z==0 adds linear term. grid (4, 80, 2), 128 thr, 2 atoms/thread (f32x2).
// ============================================================
#define TPB 128
#define MAIN_SMEM (2*STAGE*8 + NPAIR*8 + NIRR*8)   // 29760

__global__ __launch_bounds__(TPB, 3) void k_main(const float* __restrict__ nf)
{
    extern __shared__ char smc[];
    ull* stg   = (ull*)smc;                            // [2][1248]
    ull* s2dup = (ull*)(smc + 2*STAGE*8);              // [1176]
    ull* s1dup = (ull*)(smc + 2*STAGE*8 + NPAIR*8);    // [48]
    uint32_t stg_u = s2u(stg);
    uint32_t s2_u  = s2u(s2dup);

    int t  = threadIdx.x;
    int c  = blockIdx.y;
    int z  = blockIdx.z;
    int nA = (blockIdx.x * TPB + t) * 2;

    const float* fa = nf + (size_t)nA * (NFEAT * NIRR) + c * NIRR;
    const float* fb = fa + NFEAT * NIRR;

    ull nf2[NIRR];
    #pragma unroll
    for (int i4 = 0; i4 < 12; i4++) {
        float4 a = *(const float4*)(fa + 4 * i4);
        float4 b = *(const float4*)(fb + 4 * i4);
        nf2[4*i4+0] = pack2(a.x, b.x);
        nf2[4*i4+1] = pack2(a.y, b.y);
        nf2[4*i4+2] = pack2(a.z, b.z);
        nf2[4*i4+3] = pack2(a.w, b.w);
    }
    for (int j = t; j < NPAIR / 2; j += TPB)
        cpa16f(s2_u + 16 * j, (const char*)(g_S2W + c * NPAIR) + 16 * j);
    cp_commit();
    if (t < NIRR) { float v = g_S1W[c * NIRR + t]; s1dup[t] = pack2(v, v); }

    const float2* uwc = g_UW3 + (size_t)c * NELEM;

    auto stage = [&](int p, int buf, int off3) {
        int lo  = loff_f(p);
        int nch = (STAGE - lo) >> 1;
        const char* src = (const char*)(uwc + off3);
        uint32_t dst = stg_u + (buf * STAGE + lo) * 8;
        for (int j = t; j < nch; j += TPB) cpa16f(dst + 16 * j, src + 16 * j);
        cp_commit();
    };

    ull acc = 0ull;
    int off_cur = (z == 0) ? 0 : STAGE;
    stage(z, 0, off_cur);

    for (int p = z; p < NIRR; p += 2) {
        int buf = ((p - z) >> 1) & 1;
        __syncthreads();
        int off_next = off_cur + tpad_f(p) + tpad_f(p + 1);
        if (p + 2 < NIRR) { stage(p + 2, buf ^ 1, off_next); cp_wait1(); }
        else              { cp_wait0(); }
        __syncthreads();

        ull x2p = pack2(fa[p], fb[p]);
        int rbase = p * NIRR - p * (p - 1) / 2 - p;
        const ull* sb = stg + buf * STAGE;

        int lofq = 0;
        #pragma unroll
        for (int q = 0; q < NIRR; q++) {
            const int q4 = q >> 2;
            if (q >= p) {
                ull t0 = s2dup[rbase + q], t1 = 0ull, t2 = 0ull, t3 = 0ull;
                const ulonglong2* row = (const ulonglong2*)(sb + lofq);
                #pragma unroll
                for (int i4 = q4; i4 < 12; i4++) {
                    ulonglong2 u0 = row[2 * (i4 - q4)];
                    ulonglong2 u1 = row[2 * (i4 - q4) + 1];
                    t0 = fma2(nf2[4*i4+0], u0.x, t0);
                    t1 = fma2(nf2[4*i4+1], u0.y, t1);
                    t2 = fma2(nf2[4*i4+2], u1.x, t2);
                    t3 = fma2(nf2[4*i4+3], u1.y, t3);
                }
                ull w = mul2(x2p, nf2[q]);
                acc = fma2(w, add2(add2(t0, t1), add2(t2, t3)), acc);
            }
            lofq += NIRR - 4 * q4;
        }
        off_cur = off_next;
    }

    if (z == 0) {
        #pragma unroll
        for (int q = 0; q < NIRR; q++) acc = fma2(nf2[q], s1dup[q], acc);
    }

    float oa, ob; unpack2(acc, oa, ob);
    g_part[z * OUTSZ + nA * NFEAT + c]       = oa;
    g_part[z * OUTSZ + (nA + 1) * NFEAT + c] = ob;
}

// ============================================================
__global__ void k_reduce(float* __restrict__ out) {
    int i = blockIdx.x * 256 + threadIdx.x;
    if (i < OUTSZ) out[i] = g_part[i] + g_part[OUTSZ + i];
}

// ============================================================
extern "C" void kernel_launch(void* const* d_in, const int* in_sizes, int n_in,
                              void* d_out, int out_size)
{
    const float* nf = (const float*)d_in[0];
    const float* U3 = (const float*)d_in[1];
    const float* U2 = (const float*)d_in[2];
    const float* U1 = (const float*)d_in[3];
    const float* W3 = (const float*)d_in[4];
    const float* W2 = (const float*)d_in[5];
    const float* W1 = (const float*)d_in[6];
    float* out = (float*)d_out;

    cudaFuncSetAttribute(k_gemm1, cudaFuncAttributeMaxDynamicSharedMemorySize, G1_SMEM);
    cudaFuncSetAttribute(k_main,  cudaFuncAttributeMaxDynamicSharedMemorySize, MAIN_SMEM);

    k_small<<<(NIRR*NIRR) / 256, 256>>>(U2, W2, U1, W1);
    k_symm<<<NELEM / 8, 256>>>(U3);
    k_gemm1<<<dim3(MPAD / 128, 2), 128, G1_SMEM>>>(W3);
    k_main<<<dim3(N_ATOMS / (2 * TPB), NFEAT, ZSPLIT), TPB, MAIN_SMEM>>>(nf);
    k_reduce<<<(OUTSZ + 255) / 256, 256>>>(out);
}